// round 3
// baseline (speedup 1.0000x reference)
#include <cuda_runtime.h>
#include <cstddef>

// Problem constants (fixed by reference: setup_inputs)
#define NN 50000
#define EE 1600000
#define HCW 64          // heads*per-head-dim = 4*16
// feature dim D = 256

// ---------------- scratch (device globals; no allocations allowed) ----------
__device__ float g_Q[NN * HCW];
__device__ float g_K[NN * HCW];
__device__ float g_V[NN * HCW];
__device__ float g_Ss[NN * HCW];
__device__ float g_H[NN * HCW];
__device__ int g_cnt[NN];
__device__ int g_rowptr[NN + 1];
__device__ int g_cursor[NN];
__device__ int g_esrc[EE];

// ---------------- CSR build ------------------------------------------------
__global__ void zero_cnt_kernel() {
    int i = blockIdx.x * blockDim.x + threadIdx.x;
    if (i < NN) g_cnt[i] = 0;
}

__global__ void hist_kernel(const int* __restrict__ dst, int E) {
    int e = blockIdx.x * blockDim.x + threadIdx.x;
    if (e < E) atomicAdd(&g_cnt[dst[e]], 1);
}

// Single-block exclusive scan over NN counts -> rowptr + cursor.
// Warp-shuffle scan: 4 barriers per 1024-chunk instead of 20.
__global__ void scan_kernel() {
    __shared__ int warpsums[32];
    __shared__ int s_carry;
    int tid = threadIdx.x;
    int lane = tid & 31;
    int wid = tid >> 5;
    if (tid == 0) s_carry = 0;
    __syncthreads();

    for (int base = 0; base < NN; base += 1024) {
        int i = base + tid;
        int v = (i < NN) ? g_cnt[i] : 0;

        // warp inclusive scan
        int inc = v;
        #pragma unroll
        for (int off = 1; off < 32; off <<= 1) {
            int t = __shfl_up_sync(0xffffffffu, inc, off);
            if (lane >= off) inc += t;
        }
        if (lane == 31) warpsums[wid] = inc;
        __syncthreads();

        // warp 0 scans the 32 warp totals
        if (wid == 0) {
            int ws = warpsums[lane];
            #pragma unroll
            for (int off = 1; off < 32; off <<= 1) {
                int t = __shfl_up_sync(0xffffffffu, ws, off);
                if (lane >= off) ws += t;
            }
            warpsums[lane] = ws;
        }
        __syncthreads();

        int prefix = (wid > 0) ? warpsums[wid - 1] : 0;
        int total = warpsums[31];
        int incl = inc + prefix + s_carry;      // inclusive prefix w/ carry
        if (i < NN) {
            g_rowptr[i + 1] = incl;
            g_cursor[i] = incl - v;             // exclusive prefix
        }
        __syncthreads();                        // all reads of s_carry done
        if (tid == 0) s_carry += total;
        __syncthreads();
    }
    if (tid == 0) g_rowptr[0] = 0;
}

__global__ void scatter_kernel(const int* __restrict__ ei, int E) {
    int e = blockIdx.x * blockDim.x + threadIdx.x;
    if (e < E) {
        int src = ei[e];
        int dst = ei[E + e];
        int pos = atomicAdd(&g_cursor[dst], 1);
        g_esrc[pos] = src;
    }
}

// ---------------- GEMM: C[sel] = act(A @ W[sel]^T + b[sel]) ----------------
// A: [M, Kd] row-major. W[sel]: [64, Kd] row-major. C[sel]: [M, *] ld=ldC.
// blockIdx.y selects one of 4 (W, b, C) triples -> computes a 64-wide slab.
// Double-buffered smem pipeline: one __syncthreads per K-tile; global load
// for tile t+1 issued before tile-t compute (latency hidden by 512 FFMA).
struct Gemm4 {
    const float* W[4];
    const float* b[4];
    float* C[4];
    int ldC;
};

#define BM 256
#define BN 64
#define BK 16
#define AP (BM + 4)     // 260 floats (16B-aligned stride)
#define WP (BN + 4)     // 68

__global__ __launch_bounds__(256) void gemm_kernel(
    const float* __restrict__ A, int M, int Kd, Gemm4 out, int act)
{
    __shared__ float As[2][BK][AP];
    __shared__ float Ws[2][BK][WP];

    int tid = threadIdx.x;
    int bm = blockIdx.x * BM;
    int sel = blockIdx.y;
    const float* __restrict__ W = out.W[sel];
    const float* __restrict__ bias = out.b[sel];
    float* __restrict__ C = out.C[sel];
    int ldC = out.ldC;

    float acc[8][8] = {};

    int arow = tid >> 2;          // 0..63
    int ak   = (tid & 3) * 4;     // 0,4,8,12
    int tm = (tid >> 3) * 8;      // 0..248
    int tn = (tid & 7) * 8;       // 0..56
    int wn = tid >> 2;            // 0..63 (W row)

    float4 ar[4], wr;

    auto load_regs = [&](int k0) {
        #pragma unroll
        for (int r = 0; r < 4; r++) {
            int row = bm + arow + r * 64;
            ar[r] = make_float4(0.f, 0.f, 0.f, 0.f);
            if (row < M)
                ar[r] = *(const float4*)(A + (size_t)row * Kd + k0 + ak);
        }
        wr = *(const float4*)(W + (size_t)wn * Kd + k0 + ak);
    };
    auto store_smem = [&](int buf) {
        #pragma unroll
        for (int r = 0; r < 4; r++) {
            As[buf][ak + 0][arow + r * 64] = ar[r].x;
            As[buf][ak + 1][arow + r * 64] = ar[r].y;
            As[buf][ak + 2][arow + r * 64] = ar[r].z;
            As[buf][ak + 3][arow + r * 64] = ar[r].w;
        }
        Ws[buf][ak + 0][wn] = wr.x;
        Ws[buf][ak + 1][wn] = wr.y;
        Ws[buf][ak + 2][wn] = wr.z;
        Ws[buf][ak + 3][wn] = wr.w;
    };

    int T = Kd / BK;
    load_regs(0);
    store_smem(0);
    __syncthreads();

    for (int t = 0; t < T; t++) {
        int buf = t & 1;
        if (t + 1 < T) load_regs((t + 1) * BK);   // in-flight during compute

        #pragma unroll
        for (int kk = 0; kk < BK; kk++) {
            float4 a0 = *(const float4*)&As[buf][kk][tm];
            float4 a1 = *(const float4*)&As[buf][kk][tm + 4];
            float4 b0 = *(const float4*)&Ws[buf][kk][tn];
            float4 b1 = *(const float4*)&Ws[buf][kk][tn + 4];
            float aa[8] = {a0.x, a0.y, a0.z, a0.w, a1.x, a1.y, a1.z, a1.w};
            float bb[8] = {b0.x, b0.y, b0.z, b0.w, b1.x, b1.y, b1.z, b1.w};
            #pragma unroll
            for (int i = 0; i < 8; i++)
                #pragma unroll
                for (int j = 0; j < 8; j++)
                    acc[i][j] += aa[i] * bb[j];
        }

        if (t + 1 < T) store_smem(buf ^ 1);
        __syncthreads();
    }

    float bb[8];
    #pragma unroll
    for (int j = 0; j < 8; j++) bb[j] = bias[tn + j];
    #pragma unroll
    for (int i = 0; i < 8; i++) {
        int m = bm + tm + i;
        if (m < M) {
            float v[8];
            #pragma unroll
            for (int j = 0; j < 8; j++) {
                v[j] = acc[i][j] + bb[j];
                if (act == 1)      v[j] = fmaxf(v[j], 0.f);
                else if (act == 2) v[j] = 1.f / (1.f + __expf(-v[j]));
            }
            float* cp = C + (size_t)m * ldC + tn;
            *(float4*)(cp)     = make_float4(v[0], v[1], v[2], v[3]);
            *(float4*)(cp + 4) = make_float4(v[4], v[5], v[6], v[7]);
        }
    }
}

// ---------------- per-node attention (one warp per dst node) ----------------
// Lane l owns float2 element l (features 2l, 2l+1), both in head l>>3.
// Online softmax over the node's incoming edges; epilogue adds skip + relu.
// Next-edge K/V prefetch overlaps L2 latency with the shfl+exp chain.
__global__ __launch_bounds__(256) void attn_kernel(
    const float* __restrict__ Qf, const float* __restrict__ Kf,
    const float* __restrict__ Vf, const float* __restrict__ Sf,
    float* __restrict__ out)
{
    int gwarp = (blockIdx.x * blockDim.x + threadIdx.x) >> 5;
    int lane = threadIdx.x & 31;
    if (gwarp >= NN) return;
    int n = gwarp;

    const float2* __restrict__ Q2 = (const float2*)Qf;
    const float2* __restrict__ K2 = (const float2*)Kf;
    const float2* __restrict__ V2 = (const float2*)Vf;

    float2 q = Q2[n * 32 + lane];
    float m = -1e30f, d = 0.f, ax = 0.f, ay = 0.f;

    int beg = g_rowptr[n];
    int end = g_rowptr[n + 1];

    float2 kv, vv;
    if (beg < end) {
        int s0 = g_esrc[beg];
        kv = K2[s0 * 32 + lane];
        vv = V2[s0 * 32 + lane];
    }
    for (int e = beg; e < end; e++) {
        float2 ck = kv, cv = vv;
        if (e + 1 < end) {                    // prefetch next edge
            int s1 = g_esrc[e + 1];
            kv = K2[s1 * 32 + lane];
            vv = V2[s1 * 32 + lane];
        }
        float p = q.x * ck.x + q.y * ck.y;
        p += __shfl_xor_sync(0xffffffffu, p, 1);
        p += __shfl_xor_sync(0xffffffffu, p, 2);
        p += __shfl_xor_sync(0xffffffffu, p, 4);
        float logit = p * 0.25f;              // 1/sqrt(16)
        float nm = fmaxf(m, logit);
        float sc = __expf(m - nm);
        float w  = __expf(logit - nm);
        d  = d  * sc + w;
        ax = ax * sc + w * cv.x;
        ay = ay * sc + w * cv.y;
        m = nm;
    }
    float inv = 1.f / (d + 1e-16f);
    float2 sk = ((const float2*)Sf)[n * 32 + lane];
    float ox = fmaxf(ax * inv + sk.x, 0.f);
    float oy = fmaxf(ay * inv + sk.y, 0.f);
    ((float2*)out)[n * 32 + lane] = make_float2(ox, oy);
}

// ---------------- launch ----------------------------------------------------
extern "C" void kernel_launch(void* const* d_in, const int* in_sizes, int n_in,
                              void* d_out, int out_size)
{
    const float* x   = (const float*)d_in[0];
    const int*   ei  = (const int*)d_in[1];
    const float* Wq1 = (const float*)d_in[2];
    const float* bq1 = (const float*)d_in[3];
    const float* Wk1 = (const float*)d_in[4];
    const float* bk1 = (const float*)d_in[5];
    const float* Wv1 = (const float*)d_in[6];
    const float* bv1 = (const float*)d_in[7];
    const float* Ws1 = (const float*)d_in[8];
    const float* bs1 = (const float*)d_in[9];
    const float* Wq2 = (const float*)d_in[10];
    const float* bq2 = (const float*)d_in[11];
    const float* Wk2 = (const float*)d_in[12];
    const float* bk2 = (const float*)d_in[13];
    const float* Wv2 = (const float*)d_in[14];
    const float* bv2 = (const float*)d_in[15];
    const float* Ws2 = (const float*)d_in[16];
    const float* bs2 = (const float*)d_in[17];
    const float* Wo  = (const float*)d_in[18];
    const float* bo  = (const float*)d_in[19];
    float* outp = (float*)d_out;

    int E = in_sizes[1] / 2;

    void *pQ, *pK, *pV, *pS, *pH;
    cudaGetSymbolAddress(&pQ, g_Q);
    cudaGetSymbolAddress(&pK, g_K);
    cudaGetSymbolAddress(&pV, g_V);
    cudaGetSymbolAddress(&pS, g_Ss);
    cudaGetSymbolAddress(&pH, g_H);
    float* fQ = (float*)pQ; float* fK = (float*)pK;
    float* fV = (float*)pV; float* fS = (float*)pS;
    float* fH = (float*)pH;

    // 1. CSR build (edge_index is fixed per launch, both layers share it)
    zero_cnt_kernel<<<(NN + 255) / 256, 256>>>();
    hist_kernel<<<(E + 255) / 256, 256>>>(ei + E, E);
    scan_kernel<<<1, 1024>>>();
    scatter_kernel<<<(E + 255) / 256, 256>>>(ei, E);

    dim3 ggrid((NN + BM - 1) / BM, 4);
    int attn_blocks = (NN * 32 + 255) / 256;

    // 2. Layer 1: Q,K,V,S = x @ {Wq1,Wk1,Wv1,Ws1}^T + b  (K=256)
    {
        Gemm4 o;
        o.W[0] = Wq1; o.W[1] = Wk1; o.W[2] = Wv1; o.W[3] = Ws1;
        o.b[0] = bq1; o.b[1] = bk1; o.b[2] = bv1; o.b[3] = bs1;
        o.C[0] = fQ;  o.C[1] = fK;  o.C[2] = fV;  o.C[3] = fS;
        o.ldC = HCW;
        gemm_kernel<<<ggrid, 256>>>(x, NN, 256, o, 0);
    }
    // 3. Attention layer 1 -> H (relu inside)
    attn_kernel<<<attn_blocks, 256>>>(fQ, fK, fV, fS, fH);

    // 4. Layer 2: Q,K,V,S = H @ {Wq2,...}^T + b  (K=64)
    {
        Gemm4 o;
        o.W[0] = Wq2; o.W[1] = Wk2; o.W[2] = Wv2; o.W[3] = Ws2;
        o.b[0] = bq2; o.b[1] = bk2; o.b[2] = bv2; o.b[3] = bs2;
        o.C[0] = fQ;  o.C[1] = fK;  o.C[2] = fV;  o.C[3] = fS;
        o.ldC = HCW;
        gemm_kernel<<<ggrid, 256>>>(fH, NN, HCW, o, 0);
    }
    // 5. Attention layer 2 -> H (in-place reuse; prior H already consumed)
    attn_kernel<<<attn_blocks, 256>>>(fQ, fK, fV, fS, fH);

    // 6. Final: out = sigmoid(H @ Wo^T + bo). Wo [256,64] split into 4 slabs.
    {
        Gemm4 o;
        for (int i = 0; i < 4; i++) {
            o.W[i] = Wo + (size_t)i * 64 * HCW;
            o.b[i] = bo + i * 64;
            o.C[i] = outp + i * 64;
        }
        o.ldC = 256;
        gemm_kernel<<<ggrid, 256>>>(fH, NN, HCW, o, 2);
    }
}

// round 5
// speedup vs baseline: 1.0716x; 1.0716x over previous
#include <cuda_runtime.h>
#include <cstddef>

// Problem constants (fixed by reference: setup_inputs)
#define NN 50000
#define EE 1600000
#define HCW 64          // heads*per-head-dim = 4*16
// feature dim D = 256

// ---------------- scratch (device globals; no allocations allowed) ----------
__device__ float g_Q[NN * HCW];
__device__ float g_K[NN * HCW];
__device__ float g_V[NN * HCW];
__device__ float g_Ss[NN * HCW];
__device__ float g_H[NN * HCW];
__device__ int g_cnt[NN];
__device__ int g_rowptr[NN + 1];
__device__ int g_cursor[NN];
__device__ int g_esrc[EE];

// ---------------- packed f32x2 helpers (Blackwell sm_100+) ------------------
__device__ __forceinline__ unsigned long long pack2(float lo, float hi) {
    unsigned long long r;
    asm("mov.b64 %0, {%1, %2};" : "=l"(r) : "f"(lo), "f"(hi));
    return r;
}
__device__ __forceinline__ void fma2(unsigned long long& d,
                                     unsigned long long a,
                                     unsigned long long b) {
    asm("fma.rn.f32x2 %0, %1, %2, %0;" : "+l"(d) : "l"(a), "l"(b));
}
__device__ __forceinline__ void unpack2(float& lo, float& hi,
                                        unsigned long long v) {
    asm("mov.b64 {%0, %1}, %2;" : "=f"(lo), "=f"(hi) : "l"(v));
}

// ---------------- CSR build ------------------------------------------------
__global__ void zero_cnt_kernel() {
    int i = blockIdx.x * blockDim.x + threadIdx.x;
    if (i < NN) g_cnt[i] = 0;
}

// 4 edges per thread: int4 load + 4 independent atomics in flight (MLP=4).
__global__ void hist_kernel(const int* __restrict__ dst, int E) {
    int e = (blockIdx.x * blockDim.x + threadIdx.x) * 4;
    if (e + 3 < E) {
        int4 d = *(const int4*)(dst + e);
        atomicAdd(&g_cnt[d.x], 1);
        atomicAdd(&g_cnt[d.y], 1);
        atomicAdd(&g_cnt[d.z], 1);
        atomicAdd(&g_cnt[d.w], 1);
    } else {
        for (; e < E; e++) atomicAdd(&g_cnt[dst[e]], 1);
    }
}

// Single-block exclusive scan over NN counts -> rowptr + cursor.
__global__ void scan_kernel() {
    __shared__ int warpsums[32];
    __shared__ int s_carry;
    int tid = threadIdx.x;
    int lane = tid & 31;
    int wid = tid >> 5;
    if (tid == 0) s_carry = 0;
    __syncthreads();

    for (int base = 0; base < NN; base += 1024) {
        int i = base + tid;
        int v = (i < NN) ? g_cnt[i] : 0;

        int inc = v;
        #pragma unroll
        for (int off = 1; off < 32; off <<= 1) {
            int t = __shfl_up_sync(0xffffffffu, inc, off);
            if (lane >= off) inc += t;
        }
        if (lane == 31) warpsums[wid] = inc;
        __syncthreads();

        if (wid == 0) {
            int ws = warpsums[lane];
            #pragma unroll
            for (int off = 1; off < 32; off <<= 1) {
                int t = __shfl_up_sync(0xffffffffu, ws, off);
                if (lane >= off) ws += t;
            }
            warpsums[lane] = ws;
        }
        __syncthreads();

        int prefix = (wid > 0) ? warpsums[wid - 1] : 0;
        int total = warpsums[31];
        int incl = inc + prefix + s_carry;
        if (i < NN) {
            g_rowptr[i + 1] = incl;
            g_cursor[i] = incl - v;
        }
        __syncthreads();
        if (tid == 0) s_carry += total;
        __syncthreads();
    }
    if (tid == 0) g_rowptr[0] = 0;
}

// 4 edges per thread, int4 loads for src and dst.
__global__ void scatter_kernel(const int* __restrict__ ei, int E) {
    int e = (blockIdx.x * blockDim.x + threadIdx.x) * 4;
    if (e + 3 < E) {
        int4 s = *(const int4*)(ei + e);
        int4 d = *(const int4*)(ei + E + e);
        int p0 = atomicAdd(&g_cursor[d.x], 1);
        int p1 = atomicAdd(&g_cursor[d.y], 1);
        int p2 = atomicAdd(&g_cursor[d.z], 1);
        int p3 = atomicAdd(&g_cursor[d.w], 1);
        g_esrc[p0] = s.x;
        g_esrc[p1] = s.y;
        g_esrc[p2] = s.z;
        g_esrc[p3] = s.w;
    } else {
        for (; e < E; e++) {
            int pos = atomicAdd(&g_cursor[ei[E + e]], 1);
            g_esrc[pos] = ei[e];
        }
    }
}

// ---------------- GEMM: C[sel] = act(A @ W[sel]^T + b[sel]) ----------------
// Double-buffered smem pipeline + packed fma.rn.f32x2 inner loop (2x fp32
// FMA throughput on sm_103a, bit-exact fp32).
struct Gemm4 {
    const float* W[4];
    const float* b[4];
    float* C[4];
    int ldC;
};

#define BM 256
#define BN 64
#define BK 16
#define AP (BM + 4)
#define WP (BN + 4)

__global__ __launch_bounds__(256) void gemm_kernel(
    const float* __restrict__ A, int M, int Kd, Gemm4 out, int act)
{
    __shared__ float As[2][BK][AP];
    __shared__ float Ws[2][BK][WP];

    int tid = threadIdx.x;
    int bm = blockIdx.x * BM;
    int sel = blockIdx.y;
    const float* __restrict__ W = out.W[sel];
    const float* __restrict__ bias = out.b[sel];
    float* __restrict__ C = out.C[sel];
    int ldC = out.ldC;

    // 8x8 tile as 8 rows x 4 packed f32x2 pairs
    unsigned long long acc[8][4];
    #pragma unroll
    for (int i = 0; i < 8; i++)
        #pragma unroll
        for (int p = 0; p < 4; p++) acc[i][p] = 0ull;

    int arow = tid >> 2;
    int ak   = (tid & 3) * 4;
    int tm = (tid >> 3) * 8;
    int tn = (tid & 7) * 8;
    int wn = tid >> 2;

    float4 ar[4], wr;

    auto load_regs = [&](int k0) {
        #pragma unroll
        for (int r = 0; r < 4; r++) {
            int row = bm + arow + r * 64;
            ar[r] = make_float4(0.f, 0.f, 0.f, 0.f);
            if (row < M)
                ar[r] = *(const float4*)(A + (size_t)row * Kd + k0 + ak);
        }
        wr = *(const float4*)(W + (size_t)wn * Kd + k0 + ak);
    };
    auto store_smem = [&](int buf) {
        #pragma unroll
        for (int r = 0; r < 4; r++) {
            As[buf][ak + 0][arow + r * 64] = ar[r].x;
            As[buf][ak + 1][arow + r * 64] = ar[r].y;
            As[buf][ak + 2][arow + r * 64] = ar[r].z;
            As[buf][ak + 3][arow + r * 64] = ar[r].w;
        }
        Ws[buf][ak + 0][wn] = wr.x;
        Ws[buf][ak + 1][wn] = wr.y;
        Ws[buf][ak + 2][wn] = wr.z;
        Ws[buf][ak + 3][wn] = wr.w;
    };

    int T = Kd / BK;
    load_regs(0);
    store_smem(0);
    __syncthreads();

    for (int t = 0; t < T; t++) {
        int buf = t & 1;
        if (t + 1 < T) load_regs((t + 1) * BK);

        #pragma unroll
        for (int kk = 0; kk < BK; kk++) {
            float4 a0 = *(const float4*)&As[buf][kk][tm];
            float4 a1 = *(const float4*)&As[buf][kk][tm + 4];
            float4 b0 = *(const float4*)&Ws[buf][kk][tn];
            float4 b1 = *(const float4*)&Ws[buf][kk][tn + 4];
            unsigned long long bp[4];
            bp[0] = pack2(b0.x, b0.y);
            bp[1] = pack2(b0.z, b0.w);
            bp[2] = pack2(b1.x, b1.y);
            bp[3] = pack2(b1.z, b1.w);
            float aa[8] = {a0.x, a0.y, a0.z, a0.w, a1.x, a1.y, a1.z, a1.w};
            #pragma unroll
            for (int i = 0; i < 8; i++) {
                unsigned long long ap = pack2(aa[i], aa[i]);
                #pragma unroll
                for (int p = 0; p < 4; p++)
                    fma2(acc[i][p], ap, bp[p]);
            }
        }

        if (t + 1 < T) store_smem(buf ^ 1);
        __syncthreads();
    }

    float bb[8];
    #pragma unroll
    for (int j = 0; j < 8; j++) bb[j] = bias[tn + j];
    #pragma unroll
    for (int i = 0; i < 8; i++) {
        int m = bm + tm + i;
        if (m < M) {
            float v[8];
            #pragma unroll
            for (int p = 0; p < 4; p++)
                unpack2(v[2 * p], v[2 * p + 1], acc[i][p]);
            #pragma unroll
            for (int j = 0; j < 8; j++) {
                v[j] += bb[j];
                if (act == 1)      v[j] = fmaxf(v[j], 0.f);
                else if (act == 2) v[j] = 1.f / (1.f + __expf(-v[j]));
            }
            float* cp = C + (size_t)m * ldC + tn;
            *(float4*)(cp)     = make_float4(v[0], v[1], v[2], v[3]);
            *(float4*)(cp + 4) = make_float4(v[4], v[5], v[6], v[7]);
        }
    }
}

// ---------------- per-node attention (one warp per dst node) ----------------
__global__ __launch_bounds__(256) void attn_kernel(
    const float* __restrict__ Qf, const float* __restrict__ Kf,
    const float* __restrict__ Vf, const float* __restrict__ Sf,
    float* __restrict__ out)
{
    int gwarp = (blockIdx.x * blockDim.x + threadIdx.x) >> 5;
    int lane = threadIdx.x & 31;
    if (gwarp >= NN) return;
    int n = gwarp;

    const float2* __restrict__ Q2 = (const float2*)Qf;
    const float2* __restrict__ K2 = (const float2*)Kf;
    const float2* __restrict__ V2 = (const float2*)Vf;

    float2 q = Q2[n * 32 + lane];
    float m = -1e30f, d = 0.f, ax = 0.f, ay = 0.f;

    int beg = g_rowptr[n];
    int end = g_rowptr[n + 1];

    float2 kv, vv;
    if (beg < end) {
        int s0 = g_esrc[beg];
        kv = K2[s0 * 32 + lane];
        vv = V2[s0 * 32 + lane];
    }
    for (int e = beg; e < end; e++) {
        float2 ck = kv, cv = vv;
        if (e + 1 < end) {
            int s1 = g_esrc[e + 1];
            kv = K2[s1 * 32 + lane];
            vv = V2[s1 * 32 + lane];
        }
        float p = q.x * ck.x + q.y * ck.y;
        p += __shfl_xor_sync(0xffffffffu, p, 1);
        p += __shfl_xor_sync(0xffffffffu, p, 2);
        p += __shfl_xor_sync(0xffffffffu, p, 4);
        float logit = p * 0.25f;
        float nm = fmaxf(m, logit);
        float sc = __expf(m - nm);
        float w  = __expf(logit - nm);
        d  = d  * sc + w;
        ax = ax * sc + w * cv.x;
        ay = ay * sc + w * cv.y;
        m = nm;
    }
    float inv = 1.f / (d + 1e-16f);
    float2 sk = ((const float2*)Sf)[n * 32 + lane];
    float ox = fmaxf(ax * inv + sk.x, 0.f);
    float oy = fmaxf(ay * inv + sk.y, 0.f);
    ((float2*)out)[n * 32 + lane] = make_float2(ox, oy);
}

// ---------------- launch ----------------------------------------------------
extern "C" void kernel_launch(void* const* d_in, const int* in_sizes, int n_in,
                              void* d_out, int out_size)
{
    const float* x   = (const float*)d_in[0];
    const int*   ei  = (const int*)d_in[1];
    const float* Wq1 = (const float*)d_in[2];
    const float* bq1 = (const float*)d_in[3];
    const float* Wk1 = (const float*)d_in[4];
    const float* bk1 = (const float*)d_in[5];
    const float* Wv1 = (const float*)d_in[6];
    const float* bv1 = (const float*)d_in[7];
    const float* Ws1 = (const float*)d_in[8];
    const float* bs1 = (const float*)d_in[9];
    const float* Wq2 = (const float*)d_in[10];
    const float* bq2 = (const float*)d_in[11];
    const float* Wk2 = (const float*)d_in[12];
    const float* bk2 = (const float*)d_in[13];
    const float* Wv2 = (const float*)d_in[14];
    const float* bv2 = (const float*)d_in[15];
    const float* Ws2 = (const float*)d_in[16];
    const float* bs2 = (const float*)d_in[17];
    const float* Wo  = (const float*)d_in[18];
    const float* bo  = (const float*)d_in[19];
    float* outp = (float*)d_out;

    int E = in_sizes[1] / 2;

    void *pQ, *pK, *pV, *pS, *pH;
    cudaGetSymbolAddress(&pQ, g_Q);
    cudaGetSymbolAddress(&pK, g_K);
    cudaGetSymbolAddress(&pV, g_V);
    cudaGetSymbolAddress(&pS, g_Ss);
    cudaGetSymbolAddress(&pH, g_H);
    float* fQ = (float*)pQ; float* fK = (float*)pK;
    float* fV = (float*)pV; float* fS = (float*)pS;
    float* fH = (float*)pH;

    // Side stream + events for overlapping the CSR build with gemm1.
    // Created on first (non-captured) call; reused by the capture call.
    static cudaStream_t s_side = nullptr;
    static cudaEvent_t ev_fork = nullptr, ev_join = nullptr;
    static bool s_tried = false;
    if (!s_tried) {
        s_tried = true;
        if (cudaStreamCreateWithFlags(&s_side, cudaStreamNonBlocking) == cudaSuccess) {
            if (cudaEventCreateWithFlags(&ev_fork, cudaEventDisableTiming) != cudaSuccess ||
                cudaEventCreateWithFlags(&ev_join, cudaEventDisableTiming) != cudaSuccess) {
                s_side = nullptr;
            }
        } else {
            s_side = nullptr;
        }
    }

    int e4blocks = ((E + 3) / 4 + 255) / 256;
    dim3 ggrid((NN + BM - 1) / BM, 4);
    int attn_blocks = (NN * 32 + 255) / 256;

    // ---- fork: CSR build on side stream, overlapped with gemm1 ----
    if (s_side) {
        cudaEventRecord(ev_fork, 0);
        cudaStreamWaitEvent(s_side, ev_fork, 0);
        zero_cnt_kernel<<<(NN + 255) / 256, 256, 0, s_side>>>();
        hist_kernel<<<e4blocks, 256, 0, s_side>>>(ei + E, E);
        scan_kernel<<<1, 1024, 0, s_side>>>();
        scatter_kernel<<<e4blocks, 256, 0, s_side>>>(ei, E);
        cudaEventRecord(ev_join, s_side);
    } else {
        zero_cnt_kernel<<<(NN + 255) / 256, 256>>>();
        hist_kernel<<<e4blocks, 256>>>(ei + E, E);
        scan_kernel<<<1, 1024>>>();
        scatter_kernel<<<e4blocks, 256>>>(ei, E);
    }

    // Layer 1 GEMM on main stream (independent of CSR)
    {
        Gemm4 o;
        o.W[0] = Wq1; o.W[1] = Wk1; o.W[2] = Wv1; o.W[3] = Ws1;
        o.b[0] = bq1; o.b[1] = bk1; o.b[2] = bv1; o.b[3] = bs1;
        o.C[0] = fQ;  o.C[1] = fK;  o.C[2] = fV;  o.C[3] = fS;
        o.ldC = HCW;
        gemm_kernel<<<ggrid, 256>>>(x, NN, 256, o, 0);
    }

    // ---- join: attn1 needs both CSR and gemm1 ----
    if (s_side) cudaStreamWaitEvent(0, ev_join, 0);

    attn_kernel<<<attn_blocks, 256>>>(fQ, fK, fV, fS, fH);

    {
        Gemm4 o;
        o.W[0] = Wq2; o.W[1] = Wk2; o.W[2] = Wv2; o.W[3] = Ws2;
        o.b[0] = bq2; o.b[1] = bk2; o.b[2] = bv2; o.b[3] = bs2;
        o.C[0] = fQ;  o.C[1] = fK;  o.C[2] = fV;  o.C[3] = fS;
        o.ldC = HCW;
        gemm_kernel<<<ggrid, 256>>>(fH, NN, HCW, o, 0);
    }
    attn_kernel<<<attn_blocks, 256>>>(fQ, fK, fV, fS, fH);

    {
        Gemm4 o;
        for (int i = 0; i < 4; i++) {
            o.W[i] = Wo + (size_t)i * 64 * HCW;
            o.b[i] = bo + i * 64;
            o.C[i] = outp + i * 64;
        }
        o.ldC = 256;
        gemm_kernel<<<ggrid, 256>>>(fH, NN, HCW, o, 2);
    }
}

// round 16
// speedup vs baseline: 1.0771x; 1.0052x over previous
#include <cuda_runtime.h>
#include <cuda_fp16.h>
#include <cstddef>

// Problem constants (fixed by reference: setup_inputs)
#define NN 50000
#define EE 1600000
#define HCW 64          // heads*per-head-dim = 4*16
// feature dim D = 256

// ---------------- scratch (device globals; no allocations allowed) ----------
__device__ float g_Q[NN * HCW];
__device__ float g_Ss[NN * HCW];
__device__ float g_H[NN * HCW];
// K/V interleaved fp16: per node 64 half2 slots; pair l: K at 2l, V at 2l+1.
__device__ __half2 g_KV[NN * 64];
__device__ int g_cnt[NN];
__device__ int g_rowptr[NN + 1];
__device__ int g_cursor[NN];
__device__ int g_esrc[EE];

// ---------------- packed f32x2 helpers (Blackwell sm_100+) ------------------
__device__ __forceinline__ unsigned long long pack2(float lo, float hi) {
    unsigned long long r;
    asm("mov.b64 %0, {%1, %2};" : "=l"(r) : "f"(lo), "f"(hi));
    return r;
}
__device__ __forceinline__ void fma2(unsigned long long& d,
                                     unsigned long long a,
                                     unsigned long long b) {
    asm("fma.rn.f32x2 %0, %1, %2, %0;" : "+l"(d) : "l"(a), "l"(b));
}
__device__ __forceinline__ void unpack2(float& lo, float& hi,
                                        unsigned long long v) {
    asm("mov.b64 {%0, %1}, %2;" : "=f"(lo), "=f"(hi) : "l"(v));
}

// ---------------- CSR build ------------------------------------------------
__global__ void hist_kernel(const int* __restrict__ dst, int E) {
    int e = (blockIdx.x * blockDim.x + threadIdx.x) * 4;
    if (e + 3 < E) {
        int4 d = *(const int4*)(dst + e);
        atomicAdd(&g_cnt[d.x], 1);
        atomicAdd(&g_cnt[d.y], 1);
        atomicAdd(&g_cnt[d.z], 1);
        atomicAdd(&g_cnt[d.w], 1);
    } else {
        for (; e < E; e++) atomicAdd(&g_cnt[dst[e]], 1);
    }
}

__global__ void scan_kernel() {
    __shared__ int warpsums[32];
    __shared__ int s_carry;
    int tid = threadIdx.x;
    int lane = tid & 31;
    int wid = tid >> 5;
    if (tid == 0) s_carry = 0;
    __syncthreads();

    for (int base = 0; base < NN; base += 1024) {
        int i = base + tid;
        int v = (i < NN) ? g_cnt[i] : 0;

        int inc = v;
        #pragma unroll
        for (int off = 1; off < 32; off <<= 1) {
            int t = __shfl_up_sync(0xffffffffu, inc, off);
            if (lane >= off) inc += t;
        }
        if (lane == 31) warpsums[wid] = inc;
        __syncthreads();

        if (wid == 0) {
            int ws = warpsums[lane];
            #pragma unroll
            for (int off = 1; off < 32; off <<= 1) {
                int t = __shfl_up_sync(0xffffffffu, ws, off);
                if (lane >= off) ws += t;
            }
            warpsums[lane] = ws;
        }
        __syncthreads();

        int prefix = (wid > 0) ? warpsums[wid - 1] : 0;
        int total = warpsums[31];
        int incl = inc + prefix + s_carry;
        if (i < NN) {
            g_rowptr[i + 1] = incl;
            g_cursor[i] = incl - v;
        }
        __syncthreads();
        if (tid == 0) s_carry += total;
        __syncthreads();
    }
    if (tid == 0) g_rowptr[0] = 0;
}

__global__ void scatter_kernel(const int* __restrict__ ei, int E) {
    int e = (blockIdx.x * blockDim.x + threadIdx.x) * 4;
    if (e + 3 < E) {
        int4 s = *(const int4*)(ei + e);
        int4 d = *(const int4*)(ei + E + e);
        int p0 = atomicAdd(&g_cursor[d.x], 1);
        int p1 = atomicAdd(&g_cursor[d.y], 1);
        int p2 = atomicAdd(&g_cursor[d.z], 1);
        int p3 = atomicAdd(&g_cursor[d.w], 1);
        g_esrc[p0] = s.x;
        g_esrc[p1] = s.y;
        g_esrc[p2] = s.z;
        g_esrc[p3] = s.w;
    } else {
        for (; e < E; e++) {
            int pos = atomicAdd(&g_cursor[ei[E + e]], 1);
            g_esrc[pos] = ei[e];
        }
    }
}

// ---------------- GEMM: C[sel] = act(A @ W[sel]^T + b[sel]) ----------------
// Double-buffered smem pipeline + packed fma.rn.f32x2 inner loop.
// kv != null: sel 1 (K) and sel 2 (V) write fp16 into the interleaved KV
// buffer instead of C[sel].
struct Gemm4 {
    const float* W[4];
    const float* b[4];
    float* C[4];
    int ldC;
};

#define BM 256
#define BN 64
#define BK 16
#define AP (BM + 4)
#define WP (BN + 4)

__global__ __launch_bounds__(256) void gemm_kernel(
    const float* __restrict__ A, int M, int Kd, Gemm4 out, int act,
    __half2* __restrict__ kv)
{
    __shared__ float As[2][BK][AP];
    __shared__ float Ws[2][BK][WP];

    int tid = threadIdx.x;
    int bm = blockIdx.x * BM;
    int sel = blockIdx.y;
    const float* __restrict__ W = out.W[sel];
    const float* __restrict__ bias = out.b[sel];
    float* __restrict__ C = out.C[sel];
    int ldC = out.ldC;

    unsigned long long acc[8][4];
    #pragma unroll
    for (int i = 0; i < 8; i++)
        #pragma unroll
        for (int p = 0; p < 4; p++) acc[i][p] = 0ull;

    int arow = tid >> 2;
    int ak   = (tid & 3) * 4;
    int tm = (tid >> 3) * 8;
    int tn = (tid & 7) * 8;
    int wn = tid >> 2;

    float4 ar[4], wr;

    auto load_regs = [&](int k0) {
        #pragma unroll
        for (int r = 0; r < 4; r++) {
            int row = bm + arow + r * 64;
            ar[r] = make_float4(0.f, 0.f, 0.f, 0.f);
            if (row < M)
                ar[r] = *(const float4*)(A + (size_t)row * Kd + k0 + ak);
        }
        wr = *(const float4*)(W + (size_t)wn * Kd + k0 + ak);
    };
    auto store_smem = [&](int buf) {
        #pragma unroll
        for (int r = 0; r < 4; r++) {
            As[buf][ak + 0][arow + r * 64] = ar[r].x;
            As[buf][ak + 1][arow + r * 64] = ar[r].y;
            As[buf][ak + 2][arow + r * 64] = ar[r].z;
            As[buf][ak + 3][arow + r * 64] = ar[r].w;
        }
        Ws[buf][ak + 0][wn] = wr.x;
        Ws[buf][ak + 1][wn] = wr.y;
        Ws[buf][ak + 2][wn] = wr.z;
        Ws[buf][ak + 3][wn] = wr.w;
    };

    int T = Kd / BK;
    load_regs(0);
    store_smem(0);
    __syncthreads();

    for (int t = 0; t < T; t++) {
        int buf = t & 1;
        if (t + 1 < T) load_regs((t + 1) * BK);

        #pragma unroll
        for (int kk = 0; kk < BK; kk++) {
            float4 a0 = *(const float4*)&As[buf][kk][tm];
            float4 a1 = *(const float4*)&As[buf][kk][tm + 4];
            float4 b0 = *(const float4*)&Ws[buf][kk][tn];
            float4 b1 = *(const float4*)&Ws[buf][kk][tn + 4];
            unsigned long long bp[4];
            bp[0] = pack2(b0.x, b0.y);
            bp[1] = pack2(b0.z, b0.w);
            bp[2] = pack2(b1.x, b1.y);
            bp[3] = pack2(b1.z, b1.w);
            float aa[8] = {a0.x, a0.y, a0.z, a0.w, a1.x, a1.y, a1.z, a1.w};
            #pragma unroll
            for (int i = 0; i < 8; i++) {
                unsigned long long ap = pack2(aa[i], aa[i]);
                #pragma unroll
                for (int p = 0; p < 4; p++)
                    fma2(acc[i][p], ap, bp[p]);
            }
        }

        if (t + 1 < T) store_smem(buf ^ 1);
        __syncthreads();
    }

    bool kvsel = (kv != nullptr) && (sel == 1 || sel == 2);
    float bb[8];
    #pragma unroll
    for (int j = 0; j < 8; j++) bb[j] = bias[tn + j];
    #pragma unroll
    for (int i = 0; i < 8; i++) {
        int m = bm + tm + i;
        if (m < M) {
            float v[8];
            #pragma unroll
            for (int p = 0; p < 4; p++)
                unpack2(v[2 * p], v[2 * p + 1], acc[i][p]);
            #pragma unroll
            for (int j = 0; j < 8; j++) {
                v[j] += bb[j];
                if (act == 1)      v[j] = fmaxf(v[j], 0.f);
                else if (act == 2) v[j] = 1.f / (1.f + __expf(-v[j]));
            }
            if (kvsel) {
                // features tn..tn+7 = pairs tn/2 .. tn/2+3
                // K pair l -> slot 2l ; V pair l -> slot 2l+1
                __half2* dst = kv + (size_t)m * 64 + tn + (sel == 2 ? 1 : 0);
                #pragma unroll
                for (int p = 0; p < 4; p++)
                    dst[2 * p] = __floats2half2_rn(v[2 * p], v[2 * p + 1]);
            } else {
                float* cp = C + (size_t)m * ldC + tn;
                *(float4*)(cp)     = make_float4(v[0], v[1], v[2], v[3]);
                *(float4*)(cp + 4) = make_float4(v[4], v[5], v[6], v[7]);
            }
        }
    }
}

// ---------------- per-node attention (one warp per dst node) ----------------
// Lane l owns features {2l,2l+1} (head l>>3). One LDG.64 per edge per lane
// fetches the interleaved fp16 (K pair, V pair). 2-way interleaved online
// softmax (independent A/B accumulator sets merged at the end).
__global__ __launch_bounds__(256) void attn_kernel(
    const float* __restrict__ Qf, const __half2* __restrict__ KVh,
    const float* __restrict__ Sf, float* __restrict__ out)
{
    int gwarp = (blockIdx.x * blockDim.x + threadIdx.x) >> 5;
    int lane = threadIdx.x & 31;
    if (gwarp >= NN) return;
    int n = gwarp;

    const float2* __restrict__ Q2 = (const float2*)Qf;
    const uint2* __restrict__ KV = (const uint2*)KVh;  // 1 uint2 = K pair + V pair

    float2 q = Q2[n * 32 + lane];

    float mA = -1e30f, dA = 0.f, axA = 0.f, ayA = 0.f;
    float mB = -1e30f, dB = 0.f, axB = 0.f, ayB = 0.f;

    int beg = g_rowptr[n];
    int end = g_rowptr[n + 1];

    if ((end - beg) & 1) {                     // peel odd edge
        int s = g_esrc[beg];
        uint2 raw = KV[(size_t)s * 32 + lane];
        float2 kf = __half22float2(*(__half2*)&raw.x);
        float2 vf = __half22float2(*(__half2*)&raw.y);
        float p = q.x * kf.x + q.y * kf.y;
        p += __shfl_xor_sync(0xffffffffu, p, 1);
        p += __shfl_xor_sync(0xffffffffu, p, 2);
        p += __shfl_xor_sync(0xffffffffu, p, 4);
        mA = p * 0.25f; dA = 1.f; axA = vf.x; ayA = vf.y;
        beg++;
    }

    uint2 r0, r1;
    if (beg < end) {
        int s0 = g_esrc[beg];
        int s1 = g_esrc[beg + 1];
        r0 = KV[(size_t)s0 * 32 + lane];
        r1 = KV[(size_t)s1 * 32 + lane];
    }
    for (int e = beg; e < end; e += 2) {
        uint2 c0 = r0, c1 = r1;
        if (e + 2 < end) {                     // prefetch next pair
            int s0 = g_esrc[e + 2];
            int s1 = g_esrc[e + 3];
            r0 = KV[(size_t)s0 * 32 + lane];
            r1 = KV[(size_t)s1 * 32 + lane];
        }
        float2 k0 = __half22float2(*(__half2*)&c0.x);
        float2 v0 = __half22float2(*(__half2*)&c0.y);
        float2 k1 = __half22float2(*(__half2*)&c1.x);
        float2 v1 = __half22float2(*(__half2*)&c1.y);

        float p0 = q.x * k0.x + q.y * k0.y;
        float p1 = q.x * k1.x + q.y * k1.y;
        p0 += __shfl_xor_sync(0xffffffffu, p0, 1);
        p1 += __shfl_xor_sync(0xffffffffu, p1, 1);
        p0 += __shfl_xor_sync(0xffffffffu, p0, 2);
        p1 += __shfl_xor_sync(0xffffffffu, p1, 2);
        p0 += __shfl_xor_sync(0xffffffffu, p0, 4);
        p1 += __shfl_xor_sync(0xffffffffu, p1, 4);
        float l0 = p0 * 0.25f;
        float l1 = p1 * 0.25f;

        float nmA = fmaxf(mA, l0);
        float nmB = fmaxf(mB, l1);
        float scA = __expf(mA - nmA);
        float scB = __expf(mB - nmB);
        float w0  = __expf(l0 - nmA);
        float w1  = __expf(l1 - nmB);
        dA  = dA  * scA + w0;
        dB  = dB  * scB + w1;
        axA = axA * scA + w0 * v0.x;
        axB = axB * scB + w1 * v1.x;
        ayA = ayA * scA + w0 * v0.y;
        ayB = ayB * scB + w1 * v1.y;
        mA = nmA;
        mB = nmB;
    }

    float m = fmaxf(mA, mB);
    float eA = __expf(mA - m);
    float eB = __expf(mB - m);
    float d  = dA * eA + dB * eB;
    float ax = axA * eA + axB * eB;
    float ay = ayA * eA + ayB * eB;

    float inv = 1.f / (d + 1e-16f);
    float2 sk = ((const float2*)Sf)[n * 32 + lane];
    float ox = fmaxf(ax * inv + sk.x, 0.f);
    float oy = fmaxf(ay * inv + sk.y, 0.f);
    ((float2*)out)[n * 32 + lane] = make_float2(ox, oy);
}

// ---------------- launch ----------------------------------------------------
extern "C" void kernel_launch(void* const* d_in, const int* in_sizes, int n_in,
                              void* d_out, int out_size)
{
    const float* x   = (const float*)d_in[0];
    const int*   ei  = (const int*)d_in[1];
    const float* Wq1 = (const float*)d_in[2];
    const float* bq1 = (const float*)d_in[3];
    const float* Wk1 = (const float*)d_in[4];
    const float* bk1 = (const float*)d_in[5];
    const float* Wv1 = (const float*)d_in[6];
    const float* bv1 = (const float*)d_in[7];
    const float* Ws1 = (const float*)d_in[8];
    const float* bs1 = (const float*)d_in[9];
    const float* Wq2 = (const float*)d_in[10];
    const float* bq2 = (const float*)d_in[11];
    const float* Wk2 = (const float*)d_in[12];
    const float* bk2 = (const float*)d_in[13];
    const float* Wv2 = (const float*)d_in[14];
    const float* bv2 = (const float*)d_in[15];
    const float* Ws2 = (const float*)d_in[16];
    const float* bs2 = (const float*)d_in[17];
    const float* Wo  = (const float*)d_in[18];
    const float* bo  = (const float*)d_in[19];
    float* outp = (float*)d_out;

    int E = in_sizes[1] / 2;

    void *pQ, *pS, *pH, *pCnt, *pKV;
    cudaGetSymbolAddress(&pQ, g_Q);
    cudaGetSymbolAddress(&pS, g_Ss);
    cudaGetSymbolAddress(&pH, g_H);
    cudaGetSymbolAddress(&pCnt, g_cnt);
    cudaGetSymbolAddress(&pKV, g_KV);
    float* fQ = (float*)pQ;
    float* fS = (float*)pS;
    float* fH = (float*)pH;
    __half2* fKV = (__half2*)pKV;

    // Side stream + events for overlapping the CSR build with gemm1.
    static cudaStream_t s_side = nullptr;
    static cudaEvent_t ev_fork = nullptr, ev_join = nullptr;
    static bool s_tried = false;
    if (!s_tried) {
        s_tried = true;
        if (cudaStreamCreateWithFlags(&s_side, cudaStreamNonBlocking) == cudaSuccess) {
            if (cudaEventCreateWithFlags(&ev_fork, cudaEventDisableTiming) != cudaSuccess ||
                cudaEventCreateWithFlags(&ev_join, cudaEventDisableTiming) != cudaSuccess) {
                s_side = nullptr;
            }
        } else {
            s_side = nullptr;
        }
    }

    int e4blocks = ((E + 3) / 4 + 255) / 256;
    dim3 ggrid((NN + BM - 1) / BM, 4);
    int attn_blocks = (NN * 32 + 255) / 256;

    // ---- fork: CSR build on side stream, overlapped with gemm1 ----
    if (s_side) {
        cudaEventRecord(ev_fork, 0);
        cudaStreamWaitEvent(s_side, ev_fork, 0);
        cudaMemsetAsync(pCnt, 0, NN * sizeof(int), s_side);
        hist_kernel<<<e4blocks, 256, 0, s_side>>>(ei + E, E);
        scan_kernel<<<1, 1024, 0, s_side>>>();
        scatter_kernel<<<e4blocks, 256, 0, s_side>>>(ei, E);
        cudaEventRecord(ev_join, s_side);
    } else {
        cudaMemsetAsync(pCnt, 0, NN * sizeof(int), 0);
        hist_kernel<<<e4blocks, 256>>>(ei + E, E);
        scan_kernel<<<1, 1024>>>();
        scatter_kernel<<<e4blocks, 256>>>(ei, E);
    }

    // Layer 1 GEMM on main stream (independent of CSR)
    {
        Gemm4 o;
        o.W[0] = Wq1; o.W[1] = Wk1; o.W[2] = Wv1; o.W[3] = Ws1;
        o.b[0] = bq1; o.b[1] = bk1; o.b[2] = bv1; o.b[3] = bs1;
        o.C[0] = fQ;  o.C[1] = nullptr; o.C[2] = nullptr; o.C[3] = fS;
        o.ldC = HCW;
        gemm_kernel<<<ggrid, 256>>>(x, NN, 256, o, 0, fKV);
    }

    // ---- join: attn1 needs both CSR and gemm1 ----
    if (s_side) cudaStreamWaitEvent(0, ev_join, 0);

    attn_kernel<<<attn_blocks, 256>>>(fQ, fKV, fS, fH);

    {
        Gemm4 o;
        o.W[0] = Wq2; o.W[1] = Wk2; o.W[2] = Wv2; o.W[3] = Ws2;
        o.b[0] = bq2; o.b[1] = bk2; o.b[2] = bv2; o.b[3] = bs2;
        o.C[0] = fQ;  o.C[1] = nullptr; o.C[2] = nullptr; o.C[3] = fS;
        o.ldC = HCW;
        gemm_kernel<<<ggrid, 256>>>(fH, NN, HCW, o, 0, fKV);
    }
    attn_kernel<<<attn_blocks, 256>>>(fQ, fKV, fS, fH);

    {
        Gemm4 o;
        for (int i = 0; i < 4; i++) {
            o.W[i] = Wo + (size_t)i * 64 * HCW;
            o.b[i] = bo + i * 64;
            o.C[i] = outp + i * 64;
        }
        o.ldC = 256;
        gemm_kernel<<<ggrid, 256>>>(fH, NN, HCW, o, 2, nullptr);
    }
}